// round 11
// baseline (speedup 1.0000x reference)
#include <cuda_runtime.h>
#include <cuda_fp16.h>
#include <cstdint>

// ================= config =================
#define THREADS 256        // 8 warps; warp grid 2(M of 32) x 4(N of 32)
#define SLICES 18          // 18 * 16 = 288 persistent CTAs (2 per SM)
#define TILE_M 64          // nodes per tile
#define KDIM 128
#define NDIM 128
#define M_TOTAL 16
#define NPATH 4

// W converted to fp16, transposed to [p][n][k] (k contiguous) — 128KB, L2-resident.
__device__ __half g_wt[NPATH * NDIM * KDIM];

// ================= helpers =================

__device__ __forceinline__ uint32_t smem_u32(const void* p) {
    uint32_t a;
    asm("{ .reg .u64 t; cvta.to.shared.u64 t, %1; cvt.u32.u64 %0, t; }"
        : "=r"(a) : "l"(p));
    return a;
}

#define LDMATRIX_X4(R0, R1, R2, R3, ADDR)                                  \
    asm volatile("ldmatrix.sync.aligned.m8n8.x4.shared.b16 {%0,%1,%2,%3}, [%4];" \
        : "=r"(R0), "=r"(R1), "=r"(R2), "=r"(R3) : "r"(ADDR))

#define MMA16816(D, A, B0, B1)                                             \
    asm volatile("mma.sync.aligned.m16n8k16.row.col.f32.f16.f16.f32 "      \
        "{%0,%1,%2,%3}, {%4,%5,%6,%7}, {%8,%9}, {%0,%1,%2,%3};"            \
        : "+f"((D)[0]), "+f"((D)[1]), "+f"((D)[2]), "+f"((D)[3])           \
        : "r"((A)[0]), "r"((A)[1]), "r"((A)[2]), "r"((A)[3]),              \
          "r"(B0), "r"(B1))

#define STS64(ADDR, LO, HI)                                                \
    asm volatile("st.shared.v2.b32 [%0], {%1,%2};"                          \
        :: "r"(ADDR), "r"(LO), "r"(HI) : "memory")

#define LDS128(R0, R1, R2, R3, ADDR)                                       \
    asm volatile("ld.shared.v4.b32 {%0,%1,%2,%3}, [%4];"                    \
        : "=r"(R0), "=r"(R1), "=r"(R2), "=r"(R3) : "r"(ADDR))

#define CP_ASYNC16(DST, SRC, SZ)                                           \
    asm volatile("cp.async.cg.shared.global [%0], [%1], 16, %2;"            \
        :: "r"(DST), "l"(SRC), "r"(SZ) : "memory")

#define CP_COMMIT() asm volatile("cp.async.commit_group;" ::: "memory")
#define CP_WAIT1()  asm volatile("cp.async.wait_group 1;" ::: "memory")

// ================= prep kernel: W fp32 [p][k][n] -> fp16 [p][n][k] =================

__global__ void prep_w_kernel(const float* __restrict__ w) {
    int idx = blockIdx.x * blockDim.x + threadIdx.x;   // 65536 total
    int p = idx >> 14;
    int n = (idx >> 7) & 127;
    int k = idx & 127;
    g_wt[idx] = __float2half_rn(w[(p << 14) + (k << 7) + n]);
}

// ================= main kernel =================
// smem (96KB): F0/F1 = 16KB fp16 mma bufs (swizzled), S0/S1 = 32KB fp32 stage.
// 3-stage pipeline: cp.async(tile i+2) || convert(i+1) || MMA(i).
// B[p] (128x128 fp16) lives in registers: breg[8][2][4] = 64 regs/thread.

__global__ void __launch_bounds__(THREADS, 2)
irreps_pers_kernel(const float* __restrict__ x,
                   const int* __restrict__ seg,
                   float* __restrict__ out,
                   int n_nodes, int ntiles) {
    extern __shared__ char smem[];

    const int tid = threadIdx.x;
    const int lane = tid & 31;
    const int wid = tid >> 5;
    const int m = blockIdx.y;
    const int s = blockIdx.x;
    const int p = seg[m];

    const uint32_t sF0 = smem_u32(smem);
    const uint32_t sF1 = sF0 + 16384u;
    const uint32_t sS0 = sF0 + 32768u;
    const uint32_t sS1 = sF0 + 65536u;

    // warp tile: 32 rows x 32 cols
    const int wr = (wid >> 2) * 32;
    const int wc = (wid & 3) * 32;

    const int cnt = (ntiles - s + SLICES - 1) / SLICES;

    // staging coords: row = u*8 + rsub (rsub = wid), 16B col = fc (= lane)
    const int fc = lane;
    const int rsub = wid;
    const uint32_t swz = (uint32_t)((((fc >> 1) ^ (rsub & 7)) << 4) | ((fc & 1) << 3));

    // ---- prologue: cp.async tile 0 -> S0 ----
    {
        const int nb = s * TILE_M;
        #pragma unroll
        for (int u = 0; u < 8; ++u) {
            int row = u * 8 + rsub;
            int node = nb + row;
            uint32_t sz = (node < n_nodes) ? 16u : 0u;
            int node_c = (node < n_nodes) ? node : 0;
            const char* src = reinterpret_cast<const char*>(
                x + (((size_t)node_c * M_TOTAL + m) << 7)) + fc * 16;
            CP_ASYNC16(sS0 + (uint32_t)(row << 9) + (uint32_t)(fc << 4), src, sz);
        }
        CP_COMMIT();
    }

    // ---- stage B[p] into S1 (fp16, swizzled, 32KB), LDSM to registers ----
    {
        const __half* wt = g_wt + (p << 14);
        #pragma unroll
        for (int i = 0; i < 8; ++i) {
            int cidx = i * THREADS + tid;      // 2048 16B chunks
            int row = cidx >> 4;
            int ch  = cidx & 15;
            uint4 v = *reinterpret_cast<const uint4*>(wt + (row << 7) + (ch << 3));
            uint32_t off = (uint32_t)(row << 8) + (uint32_t)(((ch ^ (row & 7)) << 4));
            *reinterpret_cast<uint4*>(smem + 65536 + off) = v;
        }
    }
    __syncthreads();

    const int b_row = wc + (lane & 7) + ((lane >> 4) << 3);
    const uint32_t b_base = sS1 + (uint32_t)(b_row << 8);
    const int b_sw = b_row & 7;
    const int b_hi = (lane >> 3) & 1;

    uint32_t breg[8][2][4];
    #pragma unroll
    for (int ks = 0; ks < 8; ++ks) {
        const int bch = (2 * ks + b_hi) ^ b_sw;
        #pragma unroll
        for (int nt4 = 0; nt4 < 2; ++nt4)
            LDMATRIX_X4(breg[ks][nt4][0], breg[ks][nt4][1],
                        breg[ks][nt4][2], breg[ks][nt4][3],
                        b_base + (uint32_t)(nt4 << 12) + (uint32_t)(bch << 4));
    }
    __syncthreads();   // B reads done before S1 reused as stage buffer

    // ---- cp.async tile 1 -> S1 ----
    if (cnt > 1) {
        const int nb = (s + SLICES) * TILE_M;
        #pragma unroll
        for (int u = 0; u < 8; ++u) {
            int row = u * 8 + rsub;
            int node = nb + row;
            uint32_t sz = (node < n_nodes) ? 16u : 0u;
            int node_c = (node < n_nodes) ? node : 0;
            const char* src = reinterpret_cast<const char*>(
                x + (((size_t)node_c * M_TOTAL + m) << 7)) + fc * 16;
            CP_ASYNC16(sS1 + (uint32_t)(row << 9) + (uint32_t)(fc << 4), src, sz);
        }
    }
    CP_COMMIT();

    // ---- A fragment addressing ----
    const int a_hi = lane >> 4;
    const int a_sw = lane & 7;
    uint32_t aoff[2];
    #pragma unroll
    for (int mt = 0; mt < 2; ++mt)
        aoff[mt] = (uint32_t)((wr + mt * 16 + (lane & 15)) << 8);

    // ---- prologue: convert tile 0 (S0 -> F0) ----
    CP_WAIT1();
    #pragma unroll
    for (int u = 0; u < 8; ++u) {
        int row = u * 8 + rsub;
        uint32_t r0, r1, r2, r3;
        LDS128(r0, r1, r2, r3, sS0 + (uint32_t)(row << 9) + (uint32_t)(fc << 4));
        __half2 h0 = __floats2half2_rn(__uint_as_float(r0), __uint_as_float(r1));
        __half2 h1 = __floats2half2_rn(__uint_as_float(r2), __uint_as_float(r3));
        STS64(sF0 + (uint32_t)(row << 8) + swz,
              *reinterpret_cast<uint32_t*>(&h0),
              *reinterpret_cast<uint32_t*>(&h1));
    }
    __syncthreads();

    // ================= main loop =================
    for (int i = 0; i < cnt; ++i) {
        const int j = i & 1;
        const int t = s + i * SLICES;
        const uint32_t sF = j ? sF1 : sF0;

        // ---- cp.async tile i+2 -> S(i&1) ----
        if (i + 2 < cnt) {
            const uint32_t sS = j ? sS1 : sS0;
            const int nb = (s + (i + 2) * SLICES) * TILE_M;
            #pragma unroll
            for (int u = 0; u < 8; ++u) {
                int row = u * 8 + rsub;
                int node = nb + row;
                uint32_t sz = (node < n_nodes) ? 16u : 0u;
                int node_c = (node < n_nodes) ? node : 0;
                const char* src = reinterpret_cast<const char*>(
                    x + (((size_t)node_c * M_TOTAL + m) << 7)) + fc * 16;
                CP_ASYNC16(sS + (uint32_t)(row << 9) + (uint32_t)(fc << 4), src, sz);
            }
        }
        CP_COMMIT();
        CP_WAIT1();    // tile i+1 resident

        // ---- convert tile i+1: S((i+1)&1) -> F((i+1)&1) ----
        if (i + 1 < cnt) {
            const uint32_t sSn = j ? sS0 : sS1;
            const uint32_t sFn = j ? sF0 : sF1;
            #pragma unroll
            for (int u = 0; u < 8; ++u) {
                int row = u * 8 + rsub;
                uint32_t r0, r1, r2, r3;
                LDS128(r0, r1, r2, r3, sSn + (uint32_t)(row << 9) + (uint32_t)(fc << 4));
                __half2 h0 = __floats2half2_rn(__uint_as_float(r0), __uint_as_float(r1));
                __half2 h1 = __floats2half2_rn(__uint_as_float(r2), __uint_as_float(r3));
                STS64(sFn + (uint32_t)(row << 8) + swz,
                      *reinterpret_cast<uint32_t*>(&h0),
                      *reinterpret_cast<uint32_t*>(&h1));
            }
        }

        // ---- MMA on tile i from F(i&1) ----
        float acc[2][4][4];
        #pragma unroll
        for (int mt = 0; mt < 2; ++mt)
            #pragma unroll
            for (int nt = 0; nt < 4; ++nt)
                #pragma unroll
                for (int q = 0; q < 4; ++q)
                    acc[mt][nt][q] = 0.0f;

        #pragma unroll
        for (int ks = 0; ks < 8; ++ks) {
            const int ach = (2 * ks + a_hi) ^ a_sw;
            uint32_t a[2][4];
            #pragma unroll
            for (int mt = 0; mt < 2; ++mt)
                LDMATRIX_X4(a[mt][0], a[mt][1], a[mt][2], a[mt][3],
                            sF + aoff[mt] + (uint32_t)(ach << 4));
            #pragma unroll
            for (int mt = 0; mt < 2; ++mt)
                #pragma unroll
                for (int nt = 0; nt < 4; ++nt)
                    MMA16816(acc[mt][nt], a[mt],
                             breg[ks][nt >> 1][(nt & 1) * 2],
                             breg[ks][nt >> 1][(nt & 1) * 2 + 1]);
        }

        // ---- epilogue: store tile i ----
        {
            const int node0 = t * TILE_M;
            const int row_in = lane >> 2;
            const int col_in = (lane & 3) << 1;
            #pragma unroll
            for (int mt = 0; mt < 2; ++mt) {
                #pragma unroll
                for (int q2 = 0; q2 < 2; ++q2) {
                    int node = node0 + wr + mt * 16 + q2 * 8 + row_in;
                    if (node < n_nodes) {
                        float* op = out + (((size_t)node * M_TOTAL + m) << 7)
                                  + wc + col_in;
                        #pragma unroll
                        for (int nt = 0; nt < 4; ++nt) {
                            float2 v;
                            v.x = acc[mt][nt][q2 * 2];
                            v.y = acc[mt][nt][q2 * 2 + 1];
                            *reinterpret_cast<float2*>(op + nt * 8) = v;
                        }
                    }
                }
            }
        }
        __syncthreads();
    }
}

// ================= launch =================

extern "C" void kernel_launch(void* const* d_in, const int* in_sizes, int n_in,
                              void* d_out, int out_size) {
    const float* x   = (const float*)d_in[0];
    const float* w   = (const float*)d_in[1];
    const int*   seg = (const int*)d_in[2];
    float* out = (float*)d_out;

    int n_nodes = in_sizes[0] / (M_TOTAL * KDIM);     // 50000
    int ntiles = (n_nodes + TILE_M - 1) / TILE_M;     // 782

    prep_w_kernel<<<(NPATH * NDIM * KDIM) / 256, 256>>>(w);

    static bool attr_set = false;
    if (!attr_set) {
        cudaFuncSetAttribute(irreps_pers_kernel,
                             cudaFuncAttributeMaxDynamicSharedMemorySize, 98304);
        attr_set = true;
    }

    dim3 grid(SLICES, M_TOTAL);   // 18 x 16 = 288 persistent CTAs (2/SM)
    irreps_pers_kernel<<<grid, THREADS, 98304>>>(x, seg, out, n_nodes, ntiles);
}

// round 12
// speedup vs baseline: 1.0118x; 1.0118x over previous
#include <cuda_runtime.h>
#include <cuda_fp16.h>
#include <cstdint>

// ================= config =================
#define THREADS 256        // 8 warps; warp grid 2(M of 32) x 4(N of 32)
#define SLICES 19          // 19 * 16 = 304 persistent CTAs = 2 per SM x 152 SMs
#define TILE_M 64          // nodes per tile
#define KDIM 128
#define NDIM 128
#define M_TOTAL 16
#define NPATH 4

// W converted to fp16, transposed to [p][n][k] (k contiguous) — 128KB, L2-resident.
__device__ __half g_wt[NPATH * NDIM * KDIM];

// ================= helpers =================

__device__ __forceinline__ uint32_t smem_u32(const void* p) {
    uint32_t a;
    asm("{ .reg .u64 t; cvta.to.shared.u64 t, %1; cvt.u32.u64 %0, t; }"
        : "=r"(a) : "l"(p));
    return a;
}

#define LDMATRIX_X4(R0, R1, R2, R3, ADDR)                                  \
    asm volatile("ldmatrix.sync.aligned.m8n8.x4.shared.b16 {%0,%1,%2,%3}, [%4];" \
        : "=r"(R0), "=r"(R1), "=r"(R2), "=r"(R3) : "r"(ADDR))

#define MMA16816(D, A, B0, B1)                                             \
    asm volatile("mma.sync.aligned.m16n8k16.row.col.f32.f16.f16.f32 "      \
        "{%0,%1,%2,%3}, {%4,%5,%6,%7}, {%8,%9}, {%0,%1,%2,%3};"            \
        : "+f"((D)[0]), "+f"((D)[1]), "+f"((D)[2]), "+f"((D)[3])           \
        : "r"((A)[0]), "r"((A)[1]), "r"((A)[2]), "r"((A)[3]),              \
          "r"(B0), "r"(B1))

#define STS64(ADDR, LO, HI)                                                \
    asm volatile("st.shared.v2.b32 [%0], {%1,%2};"                          \
        :: "r"(ADDR), "r"(LO), "r"(HI) : "memory")

#define LDS128(R0, R1, R2, R3, ADDR)                                       \
    asm volatile("ld.shared.v4.b32 {%0,%1,%2,%3}, [%4];"                    \
        : "=r"(R0), "=r"(R1), "=r"(R2), "=r"(R3) : "r"(ADDR))

#define CP_ASYNC16(DST, SRC, SZ)                                           \
    asm volatile("cp.async.cg.shared.global [%0], [%1], 16, %2;"            \
        :: "r"(DST), "l"(SRC), "r"(SZ) : "memory")

#define CP_COMMIT() asm volatile("cp.async.commit_group;" ::: "memory")
#define CP_WAIT1()  asm volatile("cp.async.wait_group 1;" ::: "memory")

// ================= prep kernel: W fp32 [p][k][n] -> fp16 [p][n][k] =================

__global__ void prep_w_kernel(const float* __restrict__ w) {
    int idx = blockIdx.x * blockDim.x + threadIdx.x;   // 65536 total
    int p = idx >> 14;
    int n = (idx >> 7) & 127;
    int k = idx & 127;
    g_wt[idx] = __float2half_rn(w[(p << 14) + (k << 7) + n]);
}

// ================= main kernel =================
// smem (96KB): F0/F1 = 16KB fp16 mma bufs (swizzled), S0/S1 = 32KB fp32 stage.
// pipeline per iter: cp.async(i+2) -> MMA(i) -> epilogue(i) -> wait -> convert(i+1).
// B[p] (128x128 fp16) lives in registers: breg[8][2][4] = 64 regs/thread.

__global__ void __launch_bounds__(THREADS, 2)
irreps_pers_kernel(const float* __restrict__ x,
                   const int* __restrict__ seg,
                   float* __restrict__ out,
                   int n_nodes, int ntiles) {
    extern __shared__ char smem[];

    const int tid = threadIdx.x;
    const int lane = tid & 31;
    const int wid = tid >> 5;
    const int m = blockIdx.y;
    const int s = blockIdx.x;
    const int p = seg[m];

    const uint32_t sF0 = smem_u32(smem);
    const uint32_t sF1 = sF0 + 16384u;
    const uint32_t sS0 = sF0 + 32768u;
    const uint32_t sS1 = sF0 + 65536u;

    // warp tile: 32 rows x 32 cols
    const int wr = (wid >> 2) * 32;
    const int wc = (wid & 3) * 32;

    const int cnt = (ntiles - s + SLICES - 1) / SLICES;

    // staging coords: row = u*8 + rsub (rsub = wid), 16B col = fc (= lane)
    const int fc = lane;
    const int rsub = wid;
    const uint32_t swz = (uint32_t)((((fc >> 1) ^ (rsub & 7)) << 4) | ((fc & 1) << 3));

    // ---- prologue: cp.async tile 0 -> S0 ----
    {
        const int nb = s * TILE_M;
        #pragma unroll
        for (int u = 0; u < 8; ++u) {
            int row = u * 8 + rsub;
            int node = nb + row;
            uint32_t sz = (node < n_nodes) ? 16u : 0u;
            int node_c = (node < n_nodes) ? node : 0;
            const char* src = reinterpret_cast<const char*>(
                x + (((size_t)node_c * M_TOTAL + m) << 7)) + fc * 16;
            CP_ASYNC16(sS0 + (uint32_t)(row << 9) + (uint32_t)(fc << 4), src, sz);
        }
        CP_COMMIT();
    }

    // ---- stage B[p] into S1 (fp16, swizzled, 32KB), LDSM to registers ----
    {
        const __half* wt = g_wt + (p << 14);
        #pragma unroll
        for (int i = 0; i < 8; ++i) {
            int cidx = i * THREADS + tid;      // 2048 16B chunks
            int row = cidx >> 4;
            int ch  = cidx & 15;
            uint4 v = *reinterpret_cast<const uint4*>(wt + (row << 7) + (ch << 3));
            uint32_t off = (uint32_t)(row << 8) + (uint32_t)(((ch ^ (row & 7)) << 4));
            *reinterpret_cast<uint4*>(smem + 65536 + off) = v;
        }
    }
    __syncthreads();

    const int b_row = wc + (lane & 7) + ((lane >> 4) << 3);
    const uint32_t b_base = sS1 + (uint32_t)(b_row << 8);
    const int b_sw = b_row & 7;
    const int b_hi = (lane >> 3) & 1;

    uint32_t breg[8][2][4];
    #pragma unroll
    for (int ks = 0; ks < 8; ++ks) {
        const int bch = (2 * ks + b_hi) ^ b_sw;
        #pragma unroll
        for (int nt4 = 0; nt4 < 2; ++nt4)
            LDMATRIX_X4(breg[ks][nt4][0], breg[ks][nt4][1],
                        breg[ks][nt4][2], breg[ks][nt4][3],
                        b_base + (uint32_t)(nt4 << 12) + (uint32_t)(bch << 4));
    }
    __syncthreads();   // B reads done before S1 reused as stage buffer

    // ---- cp.async tile 1 -> S1 ----
    if (cnt > 1) {
        const int nb = (s + SLICES) * TILE_M;
        #pragma unroll
        for (int u = 0; u < 8; ++u) {
            int row = u * 8 + rsub;
            int node = nb + row;
            uint32_t sz = (node < n_nodes) ? 16u : 0u;
            int node_c = (node < n_nodes) ? node : 0;
            const char* src = reinterpret_cast<const char*>(
                x + (((size_t)node_c * M_TOTAL + m) << 7)) + fc * 16;
            CP_ASYNC16(sS1 + (uint32_t)(row << 9) + (uint32_t)(fc << 4), src, sz);
        }
    }
    CP_COMMIT();

    // ---- A fragment addressing ----
    const int a_hi = lane >> 4;
    const int a_sw = lane & 7;
    uint32_t aoff[2];
    #pragma unroll
    for (int mt = 0; mt < 2; ++mt)
        aoff[mt] = (uint32_t)((wr + mt * 16 + (lane & 15)) << 8);

    // ---- prologue: convert tile 0 (S0 -> F0) ----
    CP_WAIT1();
    #pragma unroll
    for (int u = 0; u < 8; ++u) {
        int row = u * 8 + rsub;
        uint32_t r0, r1, r2, r3;
        LDS128(r0, r1, r2, r3, sS0 + (uint32_t)(row << 9) + (uint32_t)(fc << 4));
        __half2 h0 = __floats2half2_rn(__uint_as_float(r0), __uint_as_float(r1));
        __half2 h1 = __floats2half2_rn(__uint_as_float(r2), __uint_as_float(r3));
        STS64(sF0 + (uint32_t)(row << 8) + swz,
              *reinterpret_cast<uint32_t*>(&h0),
              *reinterpret_cast<uint32_t*>(&h1));
    }
    __syncthreads();

    // ================= main loop =================
    for (int i = 0; i < cnt; ++i) {
        const int j = i & 1;
        const int t = s + i * SLICES;
        const uint32_t sF = j ? sF1 : sF0;

        // ---- issue cp.async tile i+2 -> S(i&1) (non-blocking) ----
        if (i + 2 < cnt) {
            const uint32_t sS = j ? sS1 : sS0;
            const int nb = (s + (i + 2) * SLICES) * TILE_M;
            #pragma unroll
            for (int u = 0; u < 8; ++u) {
                int row = u * 8 + rsub;
                int node = nb + row;
                uint32_t sz = (node < n_nodes) ? 16u : 0u;
                int node_c = (node < n_nodes) ? node : 0;
                const char* src = reinterpret_cast<const char*>(
                    x + (((size_t)node_c * M_TOTAL + m) << 7)) + fc * 16;
                CP_ASYNC16(sS + (uint32_t)(row << 9) + (uint32_t)(fc << 4), src, sz);
            }
        }
        CP_COMMIT();   // keep group counts aligned

        // ---- MMA on tile i from F(i&1) ----
        float acc[2][4][4];
        #pragma unroll
        for (int mt = 0; mt < 2; ++mt)
            #pragma unroll
            for (int nt = 0; nt < 4; ++nt)
                #pragma unroll
                for (int q = 0; q < 4; ++q)
                    acc[mt][nt][q] = 0.0f;

        #pragma unroll
        for (int ks = 0; ks < 8; ++ks) {
            const int ach = (2 * ks + a_hi) ^ a_sw;
            uint32_t a[2][4];
            #pragma unroll
            for (int mt = 0; mt < 2; ++mt)
                LDMATRIX_X4(a[mt][0], a[mt][1], a[mt][2], a[mt][3],
                            sF + aoff[mt] + (uint32_t)(ach << 4));
            #pragma unroll
            for (int mt = 0; mt < 2; ++mt)
                #pragma unroll
                for (int nt = 0; nt < 4; ++nt)
                    MMA16816(acc[mt][nt], a[mt],
                             breg[ks][nt >> 1][(nt & 1) * 2],
                             breg[ks][nt >> 1][(nt & 1) * 2 + 1]);
        }

        // ---- epilogue: store tile i ----
        {
            const int node0 = t * TILE_M;
            const int row_in = lane >> 2;
            const int col_in = (lane & 3) << 1;
            #pragma unroll
            for (int mt = 0; mt < 2; ++mt) {
                #pragma unroll
                for (int q2 = 0; q2 < 2; ++q2) {
                    int node = node0 + wr + mt * 16 + q2 * 8 + row_in;
                    if (node < n_nodes) {
                        float* op = out + (((size_t)node * M_TOTAL + m) << 7)
                                  + wc + col_in;
                        #pragma unroll
                        for (int nt = 0; nt < 4; ++nt) {
                            float2 v;
                            v.x = acc[mt][nt][q2 * 2];
                            v.y = acc[mt][nt][q2 * 2 + 1];
                            *reinterpret_cast<float2*>(op + nt * 8) = v;
                        }
                    }
                }
            }
        }

        // ---- wait tile i+1, convert S((i+1)&1) -> F((i+1)&1) ----
        CP_WAIT1();
        if (i + 1 < cnt) {
            const uint32_t sSn = j ? sS0 : sS1;
            const uint32_t sFn = j ? sF0 : sF1;
            #pragma unroll
            for (int u = 0; u < 8; ++u) {
                int row = u * 8 + rsub;
                uint32_t r0, r1, r2, r3;
                LDS128(r0, r1, r2, r3, sSn + (uint32_t)(row << 9) + (uint32_t)(fc << 4));
                __half2 h0 = __floats2half2_rn(__uint_as_float(r0), __uint_as_float(r1));
                __half2 h1 = __floats2half2_rn(__uint_as_float(r2), __uint_as_float(r3));
                STS64(sFn + (uint32_t)(row << 8) + swz,
                      *reinterpret_cast<uint32_t*>(&h0),
                      *reinterpret_cast<uint32_t*>(&h1));
            }
        }
        __syncthreads();
    }
}

// ================= launch =================

extern "C" void kernel_launch(void* const* d_in, const int* in_sizes, int n_in,
                              void* d_out, int out_size) {
    const float* x   = (const float*)d_in[0];
    const float* w   = (const float*)d_in[1];
    const int*   seg = (const int*)d_in[2];
    float* out = (float*)d_out;

    int n_nodes = in_sizes[0] / (M_TOTAL * KDIM);     // 50000
    int ntiles = (n_nodes + TILE_M - 1) / TILE_M;     // 782

    prep_w_kernel<<<(NPATH * NDIM * KDIM) / 256, 256>>>(w);

    static bool attr_set = false;
    if (!attr_set) {
        cudaFuncSetAttribute(irreps_pers_kernel,
                             cudaFuncAttributeMaxDynamicSharedMemorySize, 98304);
        attr_set = true;
    }

    dim3 grid(SLICES, M_TOTAL);   // 19 x 16 = 304 persistent CTAs (2/SM x 152 SMs)
    irreps_pers_kernel<<<grid, THREADS, 98304>>>(x, seg, out, n_nodes, ntiles);
}